// round 2
// baseline (speedup 1.0000x reference)
#include <cuda_runtime.h>
#include <cstdint>

#define N_ROWS 32768
#define DIM    128
#define KCODES 1024
#define BR     64      // rows per block
#define BKT    128     // k per tile
#define NBLK   (N_ROWS / BR)   // 512

__device__ float g_esq[KCODES];
__device__ float g_partials[NBLK];

// ---- per-code squared norm -------------------------------------------------
__global__ void esq_kernel(const float* __restrict__ emb) {
    int k = blockIdx.x * blockDim.x + threadIdx.x;
    if (k >= KCODES) return;
    const float4* e4 = reinterpret_cast<const float4*>(emb + (size_t)k * DIM);
    float a0 = 0.f, a1 = 0.f, a2 = 0.f, a3 = 0.f;
#pragma unroll
    for (int i = 0; i < DIM / 4; i++) {
        float4 v = e4[i];
        a0 = fmaf(v.x, v.x, a0);
        a1 = fmaf(v.y, v.y, a1);
        a2 = fmaf(v.z, v.z, a2);
        a3 = fmaf(v.w, v.w, a3);
    }
    g_esq[k] = (a0 + a1) + (a2 + a3);
}

// ---- main fused GEMM + argmin + gather ------------------------------------
__global__ __launch_bounds__(256, 2)
void vq_kernel(const float* __restrict__ x, const float* __restrict__ emb,
               float* __restrict__ outQ, float* __restrict__ outIdx) {
    __shared__ __align__(16) float xs[128 * 68];   // x tile, transposed [d][row], pad 68
    __shared__ __align__(16) float es[16 * 132];   // emb chunk, transposed [d][k], pad 132
    __shared__ float xsq[BR];
    __shared__ float esqs[KCODES];
    __shared__ int   kw[BR];
    __shared__ float lparr[BR];

    const int tid = threadIdx.x;
    const int tx = tid & 15;       // 16 k-groups
    const int ty = tid >> 4;       // 16 row-groups
    const int r0 = blockIdx.x * BR;

    // load & transpose x tile: 64 rows x 128 d
    const float4* x4 = reinterpret_cast<const float4*>(x + (size_t)r0 * DIM);
#pragma unroll
    for (int i = 0; i < 8; i++) {
        int f = tid + i * 256;          // 0..2047 float4s
        int r = f >> 5;                 // row
        int d4 = f & 31;                // float4 within row
        float4 v = x4[f];
        xs[(4 * d4 + 0) * 68 + r] = v.x;
        xs[(4 * d4 + 1) * 68 + r] = v.y;
        xs[(4 * d4 + 2) * 68 + r] = v.z;
        xs[(4 * d4 + 3) * 68 + r] = v.w;
    }
    for (int i = tid; i < KCODES; i += 256) esqs[i] = g_esq[i];
    __syncthreads();

    // per-row |x|^2
    if (tid < BR) {
        float a0 = 0.f, a1 = 0.f, a2 = 0.f, a3 = 0.f;
        for (int d = 0; d < DIM; d += 4) {
            float v0 = xs[(d + 0) * 68 + tid];
            float v1 = xs[(d + 1) * 68 + tid];
            float v2 = xs[(d + 2) * 68 + tid];
            float v3 = xs[(d + 3) * 68 + tid];
            a0 = fmaf(v0, v0, a0);
            a1 = fmaf(v1, v1, a1);
            a2 = fmaf(v2, v2, a2);
            a3 = fmaf(v3, v3, a3);
        }
        xsq[tid] = (a0 + a1) + (a2 + a3);
    }
    __syncthreads();

    float xsql[4];
#pragma unroll
    for (int i = 0; i < 4; i++) xsql[i] = xsq[ty * 4 + i];

    float best[4];
    int   bestk[4];
    float bestdot[4];
#pragma unroll
    for (int i = 0; i < 4; i++) { best[i] = 3.4e38f; bestk[i] = 0; bestdot[i] = 0.f; }

    const float4* e4g = reinterpret_cast<const float4*>(emb);

    for (int kt = 0; kt < KCODES / BKT; kt++) {
        float acc[4][8];
#pragma unroll
        for (int i = 0; i < 4; i++)
#pragma unroll
            for (int j = 0; j < 8; j++) acc[i][j] = 0.f;

        for (int dh = 0; dh < DIM / 16; dh++) {
            __syncthreads();
            // load emb chunk: 128 k x 16 d, transposed to [d][k]
#pragma unroll
            for (int ii = 0; ii < 2; ii++) {
                int f = tid + ii * 256;          // 0..511 float4s
                int k = f >> 2;
                int d4 = f & 3;
                float4 v = e4g[(size_t)(kt * BKT + k) * 32 + dh * 4 + d4];
                es[(4 * d4 + 0) * 132 + k] = v.x;
                es[(4 * d4 + 1) * 132 + k] = v.y;
                es[(4 * d4 + 2) * 132 + k] = v.z;
                es[(4 * d4 + 3) * 132 + k] = v.w;
            }
            __syncthreads();

#pragma unroll
            for (int d = 0; d < 16; d++) {
                float4 xa = *reinterpret_cast<const float4*>(&xs[(dh * 16 + d) * 68 + ty * 4]);
                float4 ea = *reinterpret_cast<const float4*>(&es[d * 132 + tx * 8]);
                float4 eb = *reinterpret_cast<const float4*>(&es[d * 132 + tx * 8 + 4]);
                float xr[4] = {xa.x, xa.y, xa.z, xa.w};
                float ek[8] = {ea.x, ea.y, ea.z, ea.w, eb.x, eb.y, eb.z, eb.w};
#pragma unroll
                for (int i = 0; i < 4; i++)
#pragma unroll
                    for (int j = 0; j < 8; j++)
                        acc[i][j] = fmaf(xr[i], ek[j], acc[i][j]);
            }
        }

        // fold into running argmin, mimicking reference fp32 op order:
        // d2 = (x_sq - 2*dots) + e_sq
#pragma unroll
        for (int i = 0; i < 4; i++) {
#pragma unroll
            for (int j = 0; j < 8; j++) {
                int k = kt * BKT + tx * 8 + j;
                float a = 2.0f * acc[i][j];
                float b = xsql[i] - a;
                float v = b + esqs[k];
                if (v < best[i]) { best[i] = v; bestk[i] = k; bestdot[i] = acc[i][j]; }
            }
        }
    }

    // cross-thread argmin: 16 candidates per row (reuse xs region)
    __syncthreads();
    float* candV = xs;
    int*   candK = reinterpret_cast<int*>(xs + 1024);
    float* candD = xs + 2048;
#pragma unroll
    for (int i = 0; i < 4; i++) {
        int r = ty * 4 + i;
        candV[r * 16 + tx] = best[i];
        candK[r * 16 + tx] = bestk[i];
        candD[r * 16 + tx] = bestdot[i];
    }
    __syncthreads();

    if (tid < BR) {
        float bv = candV[tid * 16];
        int   bk = candK[tid * 16];
        float bd = candD[tid * 16];
#pragma unroll
        for (int t = 1; t < 16; t++) {
            float v = candV[tid * 16 + t];
            int   k2 = candK[tid * 16 + t];
            if (v < bv || (v == bv && k2 < bk)) { bv = v; bk = k2; bd = candD[tid * 16 + t]; }
        }
        kw[tid] = bk;
        // sum_d (q - x)^2 = |e_k|^2 - 2*dot + |x|^2
        lparr[tid] = fmaf(-2.0f, bd, xsq[tid]) + esqs[bk];
    }
    __syncthreads();

    if (tid == 0) {
        float s = 0.f;
        for (int r = 0; r < BR; r++) s += lparr[r];
        g_partials[blockIdx.x] = s;
    }

    // write quantized rows (emb is L2-resident)
    float4* out4 = reinterpret_cast<float4*>(outQ + (size_t)r0 * DIM);
#pragma unroll
    for (int i = 0; i < 8; i++) {
        int f = tid + i * 256;
        int r = f >> 5;
        int d4 = f & 31;
        out4[f] = e4g[(size_t)kw[r] * 32 + d4];
    }

    if (outIdx != nullptr && tid < BR) outIdx[r0 + tid] = (float)kw[tid];
}

// ---- deterministic loss finalize -------------------------------------------
__global__ void finalize_kernel(float* __restrict__ outLoss) {
    if (threadIdx.x == 0 && blockIdx.x == 0) {
        float s = 0.f;
#pragma unroll 8
        for (int b = 0; b < NBLK; b++) s += g_partials[b];
        float d = s / (float)((size_t)N_ROWS * DIM);
        // loss = q_latent + 0.25 * e_latent, both equal to d
        outLoss[0] = d + 0.25f * d;
    }
}

extern "C" void kernel_launch(void* const* d_in, const int* in_sizes, int n_in,
                              void* d_out, int out_size) {
    const float* x   = (const float*)d_in[0];
    const float* emb = (const float*)d_in[1];
    // defensive: identify inputs by size (x: 4194304, emb: 131072)
    if (n_in >= 2 && in_sizes[0] == KCODES * DIM && in_sizes[1] == N_ROWS * DIM) {
        const float* t = x; x = emb; emb = t;
    }

    float* out = (float*)d_out;
    float* outQ = out;                                     // [N*D]
    float* outLoss = nullptr;
    float* outIdx = nullptr;
    if (out_size > N_ROWS * DIM) outLoss = out + (size_t)N_ROWS * DIM;          // [1]
    if (out_size >= N_ROWS * DIM + 1 + N_ROWS) outIdx = out + (size_t)N_ROWS * DIM + 1;  // [N]

    esq_kernel<<<KCODES / 128, 128>>>(emb);
    vq_kernel<<<NBLK, 256>>>(x, emb, outQ, outIdx);
    if (outLoss != nullptr) finalize_kernel<<<1, 32>>>(outLoss);
}

// round 9
// speedup vs baseline: 1.0861x; 1.0861x over previous
#include <cuda_runtime.h>
#include <cstdint>

#define N_ROWS  32768
#define DIM     128
#define KCODES  1024
#define MROWS   64                   // rows per CTA
#define NCTAS   (N_ROWS / MROWS)     // 512
#define NCHUNK  64                   // codes per chunk
#define NCHUNKS (KCODES / NCHUNK)    // 16
#define KD      256                  // emb storage: [hi 128 | lo 128]
#define ASTR    260                  // padded row stride (floats); row*260 is 16B-aligned

__device__ float g_esq[KCODES];
__device__ __align__(16) float g_emb2[KCODES * KD];   // [k][hi d0..127 | lo d0..127]
__device__ float g_partials[NCTAS];

// smem float offsets
#define SF_AS    0                    // 64*260 = 16640
#define SF_BS0   16640                // 16640
#define SF_BS1   33280                // 16640
#define SF_ESQ   49920                // 1024
#define SF_XSQ   50944                // 64
#define SF_CV    51008                // 512
#define SF_CK    51520                // 512
#define SF_CD    52032                // 512
#define SF_KW    52544                // 64
#define SF_LP    52608                // 64
#define SF_TOTAL 52672                // floats -> 210688 bytes

__device__ __forceinline__ float tf32f(float f) {
    uint32_t r;
    asm("cvt.rna.tf32.f32 %0, %1;" : "=r"(r) : "f"(f));
    return __uint_as_float(r);
}

// ---------------- setup kernels ----------------
__global__ void esq_kernel(const float* __restrict__ emb) {
    int w = (blockIdx.x * blockDim.x + threadIdx.x) >> 5;
    int lane = threadIdx.x & 31;
    if (w >= KCODES) return;
    float4 v = reinterpret_cast<const float4*>(emb + (size_t)w * DIM)[lane];
    float s = fmaf(v.x, v.x, fmaf(v.y, v.y, fmaf(v.z, v.z, v.w * v.w)));
#pragma unroll
    for (int o = 16; o; o >>= 1) s += __shfl_xor_sync(0xFFFFFFFFu, s, o);
    if (lane == 0) g_esq[w] = s;
}

__global__ void split_kernel(const float* __restrict__ emb) {
    int i = blockIdx.x * blockDim.x + threadIdx.x;
    if (i >= KCODES * DIM) return;
    int k = i >> 7, d = i & 127;
    float e = emb[i];
    float h = tf32f(e);
    g_emb2[k * KD + d]       = h;
    g_emb2[k * KD + 128 + d] = tf32f(e - h);
}

// ---------------- main mma.sync kernel ----------------
__device__ __forceinline__ void load_b(float* bs, int chunk, int tid) {
    const float4* e2 = reinterpret_cast<const float4*>(g_emb2);
#pragma unroll 4
    for (int i = 0; i < 32; i++) {
        int f = i * 128 + tid;          // 0..4095 float4
        int c = f >> 6;                 // code 0..63
        int q = f & 63;                 // float4 within row
        float4 v = e2[(size_t)(chunk * NCHUNK + c) * (KD / 4) + q];
        *reinterpret_cast<float4*>(&bs[c * ASTR + 4 * q]) = v;
    }
}

__global__ __launch_bounds__(128, 1)
void vq_mma_kernel(const float* __restrict__ x, const float* __restrict__ emb,
                   float* __restrict__ outQ, float* __restrict__ outIdx) {
    extern __shared__ float sm[];
    float* As    = sm + SF_AS;
    float* esqs  = sm + SF_ESQ;
    float* xsqs  = sm + SF_XSQ;
    float* candV = sm + SF_CV;
    int*   candK = reinterpret_cast<int*>(sm + SF_CK);
    float* candD = sm + SF_CD;
    int*   kw    = reinterpret_cast<int*>(sm + SF_KW);
    float* lp    = sm + SF_LP;

    const int tid  = threadIdx.x;
    const int lane = tid & 31;
    const int warp = tid >> 5;
    const int wm = warp >> 1, wn = warp & 1;    // 2x2 warp grid
    const int gid = lane >> 2, tig = lane & 3;  // mma fragment coords
    const int r0 = blockIdx.x * MROWS;

    for (int i = tid; i < KCODES; i += 128) esqs[i] = g_esq[i];

    // ---- A fill: x tile -> hi (cols 0..127) | lo (cols 128..255), tf32-rounded
    const float4* x4 = reinterpret_cast<const float4*>(x + (size_t)r0 * DIM);
#pragma unroll
    for (int i = 0; i < 16; i++) {
        int f = i * 128 + tid;          // 0..2047 float4
        int r = f >> 5, c4 = f & 31;
        float4 v = x4[f];
        float4 h = make_float4(tf32f(v.x), tf32f(v.y), tf32f(v.z), tf32f(v.w));
        float4 l = make_float4(tf32f(v.x - h.x), tf32f(v.y - h.y),
                               tf32f(v.z - h.z), tf32f(v.w - h.w));
        *reinterpret_cast<float4*>(&As[r * ASTR + 4 * c4])       = h;
        *reinterpret_cast<float4*>(&As[r * ASTR + 128 + 4 * c4]) = l;
    }

    // ---- per-row |x|^2 (same formula/order as the passing R2 kernel)
    if (tid < MROWS) {
        const float4* xr = reinterpret_cast<const float4*>(x + (size_t)(r0 + tid) * DIM);
        float a0 = 0.f, a1 = 0.f, a2 = 0.f, a3 = 0.f;
#pragma unroll
        for (int i = 0; i < 32; i++) {
            float4 v = xr[i];
            a0 = fmaf(v.x, v.x, a0); a1 = fmaf(v.y, v.y, a1);
            a2 = fmaf(v.z, v.z, a2); a3 = fmaf(v.w, v.w, a3);
        }
        xsqs[tid] = (a0 + a1) + (a2 + a3);
    }

    load_b(sm + SF_BS0, 0, tid);
    __syncthreads();

    float xsl[4];
#pragma unroll
    for (int mt = 0; mt < 2; mt++) {
        xsl[mt * 2 + 0] = xsqs[wm * 32 + mt * 16 + gid];
        xsl[mt * 2 + 1] = xsqs[wm * 32 + mt * 16 + gid + 8];
    }

    float best[4], bdot[4];
    int bk[4];
#pragma unroll
    for (int i = 0; i < 4; i++) { best[i] = 3.4e38f; bk[i] = 0; bdot[i] = 0.f; }

    for (int ch = 0; ch < NCHUNKS; ch++) {
        // prefetch next chunk into the other buffer (freed by last iteration's sync)
        if (ch + 1 < NCHUNKS) load_b(sm + ((ch + 1) & 1 ? SF_BS1 : SF_BS0), ch + 1, tid);

        const float* B = sm + ((ch & 1) ? SF_BS1 : SF_BS0);
        float acc[2][4][4];
#pragma unroll
        for (int mt = 0; mt < 2; mt++)
#pragma unroll
            for (int nt = 0; nt < 4; nt++)
#pragma unroll
                for (int j = 0; j < 4; j++) acc[mt][nt][j] = 0.f;

        // 3-group split-tf32: hi*hi + lo*hi + hi*lo (lo*lo dropped, ~2^-22 rel)
#pragma unroll
        for (int g = 0; g < 3; g++) {
            const int ao = (g == 1) ? 128 : 0;
            const int bo = (g == 2) ? 128 : 0;
#pragma unroll
            for (int ks = 0; ks < 16; ks++) {
                const int kk = ks * 8;
                uint32_t a[2][4];
#pragma unroll
                for (int mt = 0; mt < 2; mt++) {
                    const float* ap = &As[(wm * 32 + mt * 16 + gid) * ASTR + ao + kk + tig];
                    a[mt][0] = __float_as_uint(ap[0]);
                    a[mt][1] = __float_as_uint(ap[8 * ASTR]);
                    a[mt][2] = __float_as_uint(ap[4]);
                    a[mt][3] = __float_as_uint(ap[8 * ASTR + 4]);
                }
#pragma unroll
                for (int nt = 0; nt < 4; nt++) {
                    const float* bp = &B[(wn * 32 + nt * 8 + gid) * ASTR + bo + kk + tig];
                    uint32_t b0 = __float_as_uint(bp[0]);
                    uint32_t b1 = __float_as_uint(bp[4]);
#pragma unroll
                    for (int mt = 0; mt < 2; mt++) {
                        asm volatile(
                            "mma.sync.aligned.m16n8k8.row.col.f32.tf32.tf32.f32 "
                            "{%0,%1,%2,%3}, {%4,%5,%6,%7}, {%8,%9}, {%0,%1,%2,%3};"
                            : "+f"(acc[mt][nt][0]), "+f"(acc[mt][nt][1]),
                              "+f"(acc[mt][nt][2]), "+f"(acc[mt][nt][3])
                            : "r"(a[mt][0]), "r"(a[mt][1]), "r"(a[mt][2]), "r"(a[mt][3]),
                              "r"(b0), "r"(b1));
                    }
                }
            }
        }

        // fold into running argmin (codes ascending per thread; strict < => first index)
#pragma unroll
        for (int mt = 0; mt < 2; mt++)
#pragma unroll
            for (int half = 0; half < 2; half++) {
                const int ri = mt * 2 + half;
                const float xs = xsl[ri];
#pragma unroll
                for (int nt = 0; nt < 4; nt++)
#pragma unroll
                    for (int jj = 0; jj < 2; jj++) {
                        int k = ch * NCHUNK + wn * 32 + nt * 8 + tig * 2 + jj;
                        float dot = acc[mt][nt][half * 2 + jj];
                        float v = (xs - 2.0f * dot) + esqs[k];   // reference op order
                        if (v < best[ri]) { best[ri] = v; bk[ri] = k; bdot[ri] = dot; }
                    }
            }
        __syncthreads();
    }

    // ---- cross-thread reduce: 8 candidate slots per row
#pragma unroll
    for (int mt = 0; mt < 2; mt++)
#pragma unroll
        for (int half = 0; half < 2; half++) {
            const int ri = mt * 2 + half;
            const int rloc = wm * 32 + mt * 16 + gid + half * 8;
            const int slot = wn * 4 + tig;
            candV[rloc * 8 + slot] = best[ri];
            candK[rloc * 8 + slot] = bk[ri];
            candD[rloc * 8 + slot] = bdot[ri];
        }
    __syncthreads();

    if (tid < MROWS) {
        float bv = candV[tid * 8];
        int   bkk = candK[tid * 8];
        float bd = candD[tid * 8];
#pragma unroll
        for (int s = 1; s < 8; s++) {
            float v = candV[tid * 8 + s];
            int   k2 = candK[tid * 8 + s];
            if (v < bv || (v == bv && k2 < bkk)) { bv = v; bkk = k2; bd = candD[tid * 8 + s]; }
        }
        kw[tid] = bkk;
        lp[tid] = fmaf(-2.0f, bd, xsqs[tid]) + esqs[bkk];   // |x-e|^2 analytic
        if (outIdx != nullptr) outIdx[r0 + tid] = (float)bkk;
    }
    __syncthreads();

    if (tid == 0) {
        float s = 0.f;
        for (int r = 0; r < MROWS; r++) s += lp[r];
        g_partials[blockIdx.x] = s;
    }

    // ---- quantized gather (emb L2-resident)
    const float4* e4 = reinterpret_cast<const float4*>(emb);
    float4* o4 = reinterpret_cast<float4*>(outQ) + (size_t)r0 * 32;
#pragma unroll 4
    for (int i = 0; i < 16; i++) {
        int f = i * 128 + tid;
        int r = f >> 5, d4 = f & 31;
        o4[f] = e4[(size_t)kw[r] * 32 + d4];
    }
}

// ---------------- deterministic loss finalize ----------------
__global__ void finalize_kernel(float* __restrict__ outLoss) {
    if (threadIdx.x == 0 && blockIdx.x == 0) {
        float s = 0.f;
#pragma unroll 8
        for (int b = 0; b < NCTAS; b++) s += g_partials[b];
        float d = s / (float)((size_t)N_ROWS * DIM);
        outLoss[0] = d + 0.25f * d;
    }
}

extern "C" void kernel_launch(void* const* d_in, const int* in_sizes, int n_in,
                              void* d_out, int out_size) {
    const float* x   = (const float*)d_in[0];
    const float* emb = (const float*)d_in[1];
    if (n_in >= 2 && in_sizes[0] == KCODES * DIM && in_sizes[1] == N_ROWS * DIM) {
        const float* t = x; x = emb; emb = t;
    }

    float* out = (float*)d_out;
    float* outQ = out;
    float* outLoss = nullptr;
    float* outIdx = nullptr;
    if (out_size > N_ROWS * DIM) outLoss = out + (size_t)N_ROWS * DIM;
    if (out_size >= N_ROWS * DIM + 1 + N_ROWS) outIdx = out + (size_t)N_ROWS * DIM + 1;

    cudaFuncSetAttribute(vq_mma_kernel, cudaFuncAttributeMaxDynamicSharedMemorySize,
                         SF_TOTAL * (int)sizeof(float));

    esq_kernel<<<KCODES * 32 / 256, 256>>>(emb);
    split_kernel<<<KCODES * DIM / 256, 256>>>(emb);
    vq_mma_kernel<<<NCTAS, 128, SF_TOTAL * sizeof(float)>>>(x, emb, outQ, outIdx);
    if (outLoss != nullptr) finalize_kernel<<<1, 32>>>(outLoss);
}

// round 14
// speedup vs baseline: 1.5275x; 1.4064x over previous
#include <cuda_runtime.h>
#include <cstdint>

#define N_ROWS  32768
#define DIM     128
#define KCODES  1024
#define MROWS   64                   // rows per CTA
#define NCTAS   (N_ROWS / MROWS)     // 512
#define NCHUNK  64                   // codes per chunk
#define NCHUNKS (KCODES / NCHUNK)    // 16
#define KD      256                  // emb storage: [hi 128 | lo 128]
#define NT      256                  // threads per CTA (8 warps)
#define ATS     132                  // A fragment-tile stride (128 + 4 pad)
#define BTS     66                   // B fragment-tile stride (64 + 2 pad)

__device__ float g_esq[KCODES];
__device__ __align__(16) float g_emb2[KCODES * KD];   // [k][hi d0..127 | lo d0..127]
__device__ float g_partials[NCTAS];
__device__ int   g_done;                              // zero-init; reset by last block

// smem float offsets
#define SF_A     0                    // 4 mtiles * 32 ks * 132 = 16896
#define SF_B0    16896                // 16896
#define SF_B1    33792                // 16896
#define SF_ESQ   50688                // 1024
#define SF_XSQ   51712                // 64
#define SF_CV    51776                // 512
#define SF_CK    52288                // 512
#define SF_CD    52800                // 512
#define SF_KW    53312                // 64
#define SF_LP    53376                // 64
#define SF_RED   53440                // 16 (cross-warp reduce + flag)
#define SF_TOTAL 53456                // floats -> 213824 bytes

__device__ __forceinline__ float tf32f(float f) {
    uint32_t r;
    asm("cvt.rna.tf32.f32 %0, %1;" : "=r"(r) : "f"(f));
    return __uint_as_float(r);
}

// ---------------- prep: esq + tf32 split, warp-per-code ----------------
__global__ void prep_kernel(const float* __restrict__ emb) {
    int w = (blockIdx.x * blockDim.x + threadIdx.x) >> 5;   // code
    int lane = threadIdx.x & 31;
    if (w >= KCODES) return;
    float4 v = reinterpret_cast<const float4*>(emb + (size_t)w * DIM)[lane];
    float s = fmaf(v.x, v.x, fmaf(v.y, v.y, fmaf(v.z, v.z, v.w * v.w)));
#pragma unroll
    for (int o = 16; o; o >>= 1) s += __shfl_xor_sync(0xFFFFFFFFu, s, o);
    if (lane == 0) g_esq[w] = s;
    // split
    float hx = tf32f(v.x), hy = tf32f(v.y), hz = tf32f(v.z), hw = tf32f(v.w);
    float* dst = g_emb2 + (size_t)w * KD + 4 * lane;
    dst[0] = hx; dst[1] = hy; dst[2] = hz; dst[3] = hw;
    dst[128 + 0] = tf32f(v.x - hx); dst[128 + 1] = tf32f(v.y - hy);
    dst[128 + 2] = tf32f(v.z - hz); dst[128 + 3] = tf32f(v.w - hw);
}

// ---------------- main kernel ----------------
// B fragment-major fill: element (code c, kcol 4q+j) -> tile(ntile=c>>3, ks=q>>1),
// lane (g=c&7, tig=j), slot=q&1.  addr=(ntile*32+ks)*BTS + (g*4+j)*2 + slot
__device__ __forceinline__ void load_b(float* bs, int chunk, int tid) {
    const float4* e2 = reinterpret_cast<const float4*>(g_emb2);
#pragma unroll 4
    for (int i = 0; i < 16; i++) {
        int f = i * NT + tid;           // 0..4095 float4
        int c = f >> 6;                 // code 0..63
        int q = f & 63;
        float4 v = e2[(size_t)(chunk * NCHUNK + c) * (KD / 4) + q];
        int base = ((c >> 3) * 32 + (q >> 1)) * BTS + (c & 7) * 8 + (q & 1);
        bs[base + 0] = v.x;
        bs[base + 2] = v.y;
        bs[base + 4] = v.z;
        bs[base + 6] = v.w;
    }
}

__global__ __launch_bounds__(NT, 1)
void vq_mma_kernel(const float* __restrict__ x, const float* __restrict__ emb,
                   float* __restrict__ outQ, float* __restrict__ outLoss,
                   float* __restrict__ outIdx) {
    extern __shared__ float sm[];
    float* As    = sm + SF_A;
    float* esqs  = sm + SF_ESQ;
    float* xsqs  = sm + SF_XSQ;
    float* candV = sm + SF_CV;
    int*   candK = reinterpret_cast<int*>(sm + SF_CK);
    float* candD = sm + SF_CD;
    int*   kw    = reinterpret_cast<int*>(sm + SF_KW);
    float* lp    = sm + SF_LP;
    float* red   = sm + SF_RED;

    const int tid  = threadIdx.x;
    const int lane = tid & 31;
    const int warp = tid >> 5;
    const int wm = warp >> 1;                   // 0..3: m16-tile
    const int wn = warp & 1;                    // 0..1: n32-half
    const int gid = lane >> 2, tig = lane & 3;
    const int r0 = blockIdx.x * MROWS;

    for (int i = tid; i < KCODES; i += NT) esqs[i] = g_esq[i];

    // ---- A fill: fragment-major.  element (row r, kcol) -> tile(mtile=r>>4, ks),
    // lane (g=(r&15)&7, tig), slot = ((r&15)>>3) + 2*hk
    const float4* x4 = reinterpret_cast<const float4*>(x + (size_t)r0 * DIM);
#pragma unroll
    for (int i = 0; i < 8; i++) {
        int f = i * NT + tid;           // 0..2047 float4
        int r = f >> 5, c4 = f & 31;
        float4 v = x4[f];
        float hx = tf32f(v.x), hy = tf32f(v.y), hz = tf32f(v.z), hw = tf32f(v.w);
        int mtile = r >> 4, mr = r & 15;
        int g = mr & 7, slot = (mr >> 3) + 2 * (c4 & 1);
        int bh = (mtile * 32 + (c4 >> 1)) * ATS + g * 16 + slot;       // hi: ks = c4>>1
        int bl = bh + 16 * ATS;                                        // lo: ks += 16
        As[bh + 0]  = hx; As[bh + 4]  = hy; As[bh + 8]  = hz; As[bh + 12] = hw;
        As[bl + 0]  = tf32f(v.x - hx); As[bl + 4]  = tf32f(v.y - hy);
        As[bl + 8]  = tf32f(v.z - hz); As[bl + 12] = tf32f(v.w - hw);
    }

    // ---- per-row |x|^2 (same formula/order as the R2 passing kernel)
    if (tid < MROWS) {
        const float4* xr = reinterpret_cast<const float4*>(x + (size_t)(r0 + tid) * DIM);
        float a0 = 0.f, a1 = 0.f, a2 = 0.f, a3 = 0.f;
#pragma unroll
        for (int i = 0; i < 32; i++) {
            float4 v = xr[i];
            a0 = fmaf(v.x, v.x, a0); a1 = fmaf(v.y, v.y, a1);
            a2 = fmaf(v.z, v.z, a2); a3 = fmaf(v.w, v.w, a3);
        }
        xsqs[tid] = (a0 + a1) + (a2 + a3);
    }

    load_b(sm + SF_B0, 0, tid);
    __syncthreads();

    float xsl0 = xsqs[wm * 16 + gid];
    float xsl1 = xsqs[wm * 16 + gid + 8];

    float best[2] = {3.4e38f, 3.4e38f}, bdot[2] = {0.f, 0.f};
    int bk[2] = {0, 0};

    for (int ch = 0; ch < NCHUNKS; ch++) {
        if (ch + 1 < NCHUNKS) load_b(sm + ((ch + 1) & 1 ? SF_B1 : SF_B0), ch + 1, tid);

        const float* B = sm + ((ch & 1) ? SF_B1 : SF_B0);
        float acc[4][4];
#pragma unroll
        for (int nt = 0; nt < 4; nt++)
#pragma unroll
            for (int j = 0; j < 4; j++) acc[nt][j] = 0.f;

        // 3-group split-tf32: hi*hi + lo*hi + hi*lo (lo*lo dropped, ~2^-22 rel)
#pragma unroll
        for (int g = 0; g < 3; g++) {
            const int ao = (g == 1) ? 16 : 0;     // ks offset into lo_x
            const int bo = (g == 2) ? 16 : 0;     // ks offset into lo_e
#pragma unroll
            for (int ks = 0; ks < 16; ks++) {
                // A fragment: one LDS.128, already in {a0,a1,a2,a3} order
                const float4 av = *reinterpret_cast<const float4*>(
                    &As[(wm * 32 + ao + ks) * ATS + (gid * 4 + tig) * 4]);
                const uint32_t a0 = __float_as_uint(av.x), a1 = __float_as_uint(av.y);
                const uint32_t a2 = __float_as_uint(av.z), a3 = __float_as_uint(av.w);
#pragma unroll
                for (int nt = 0; nt < 4; nt++) {
                    const float2 bv = *reinterpret_cast<const float2*>(
                        &B[((wn * 4 + nt) * 32 + bo + ks) * BTS + (gid * 4 + tig) * 2]);
                    asm volatile(
                        "mma.sync.aligned.m16n8k8.row.col.f32.tf32.tf32.f32 "
                        "{%0,%1,%2,%3}, {%4,%5,%6,%7}, {%8,%9}, {%0,%1,%2,%3};"
                        : "+f"(acc[nt][0]), "+f"(acc[nt][1]),
                          "+f"(acc[nt][2]), "+f"(acc[nt][3])
                        : "r"(a0), "r"(a1), "r"(a2), "r"(a3),
                          "r"(__float_as_uint(bv.x)), "r"(__float_as_uint(bv.y)));
                }
            }
        }

        // fold into running argmin (ascending k per thread; strict < => first index)
#pragma unroll
        for (int nt = 0; nt < 4; nt++)
#pragma unroll
            for (int jj = 0; jj < 2; jj++) {
                int k = ch * NCHUNK + wn * 32 + nt * 8 + tig * 2 + jj;
                float e = esqs[k];
                float d0 = acc[nt][jj];            // row gid
                float d1 = acc[nt][2 + jj];        // row gid+8
                float v0 = (xsl0 - 2.0f * d0) + e;
                float v1 = (xsl1 - 2.0f * d1) + e;
                if (v0 < best[0]) { best[0] = v0; bk[0] = k; bdot[0] = d0; }
                if (v1 < best[1]) { best[1] = v1; bk[1] = k; bdot[1] = d1; }
            }
        __syncthreads();
    }

    // ---- cross-thread reduce: 8 candidate slots per row (wn x tig)
#pragma unroll
    for (int half = 0; half < 2; half++) {
        int rloc = wm * 16 + gid + half * 8;
        int slot = wn * 4 + tig;
        candV[rloc * 8 + slot] = best[half];
        candK[rloc * 8 + slot] = bk[half];
        candD[rloc * 8 + slot] = bdot[half];
    }
    __syncthreads();

    if (tid < MROWS) {
        float bv = candV[tid * 8];
        int   bkk = candK[tid * 8];
        float bd = candD[tid * 8];
#pragma unroll
        for (int s = 1; s < 8; s++) {
            float v = candV[tid * 8 + s];
            int   k2 = candK[tid * 8 + s];
            if (v < bv || (v == bv && k2 < bkk)) { bv = v; bkk = k2; bd = candD[tid * 8 + s]; }
        }
        kw[tid] = bkk;
        lp[tid] = fmaf(-2.0f, bd, xsqs[tid]) + esqs[bkk];
        if (outIdx != nullptr) outIdx[r0 + tid] = (float)bkk;
    }
    __syncthreads();

    // block partial
    if (tid == 0) {
        float s = 0.f;
        for (int r = 0; r < MROWS; r++) s += lp[r];
        g_partials[blockIdx.x] = s;
        __threadfence();
        int old = atomicAdd(&g_done, 1);
        red[8] = (old == NCTAS - 1) ? 1.0f : 0.0f;
    }

    // ---- quantized gather (emb L2-resident)
    const float4* e4 = reinterpret_cast<const float4*>(emb);
    float4* o4 = reinterpret_cast<float4*>(outQ) + (size_t)r0 * 32;
#pragma unroll 4
    for (int i = 0; i < 8; i++) {
        int f = i * NT + tid;
        int r = f >> 5, d4 = f & 31;
        o4[f] = e4[(size_t)kw[r] * 32 + d4];
    }

    // ---- last block finalizes the loss (deterministic fixed-order reduction)
    __syncthreads();
    if (red[8] != 0.0f) {
        __threadfence();
        float s = g_partials[tid] + g_partials[tid + NT];   // NCTAS = 2*NT
#pragma unroll
        for (int o = 16; o; o >>= 1) s += __shfl_xor_sync(0xFFFFFFFFu, s, o);
        if (lane == 0) red[warp] = s;
        __syncthreads();
        if (tid == 0) {
            float t = 0.f;
#pragma unroll
            for (int w2 = 0; w2 < 8; w2++) t += red[w2];
            float d = t / (float)((size_t)N_ROWS * DIM);
            if (outLoss != nullptr) outLoss[0] = d + 0.25f * d;
            g_done = 0;                                     // reset for next replay
        }
    }
}

extern "C" void kernel_launch(void* const* d_in, const int* in_sizes, int n_in,
                              void* d_out, int out_size) {
    const float* x   = (const float*)d_in[0];
    const float* emb = (const float*)d_in[1];
    if (n_in >= 2 && in_sizes[0] == KCODES * DIM && in_sizes[1] == N_ROWS * DIM) {
        const float* t = x; x = emb; emb = t;
    }

    float* out = (float*)d_out;
    float* outQ = out;
    float* outLoss = nullptr;
    float* outIdx = nullptr;
    if (out_size > N_ROWS * DIM) outLoss = out + (size_t)N_ROWS * DIM;
    if (out_size >= N_ROWS * DIM + 1 + N_ROWS) outIdx = out + (size_t)N_ROWS * DIM + 1;

    cudaFuncSetAttribute(vq_mma_kernel, cudaFuncAttributeMaxDynamicSharedMemorySize,
                         SF_TOTAL * (int)sizeof(float));

    prep_kernel<<<KCODES * 32 / NT, NT>>>(emb);
    vq_mma_kernel<<<NCTAS, NT, SF_TOTAL * sizeof(float)>>>(x, emb, outQ, outLoss, outIdx);
}

// round 17
// speedup vs baseline: 1.6262x; 1.0646x over previous
#include <cuda_runtime.h>
#include <cstdint>

#define N_ROWS  32768
#define DIM     128
#define KCODES  1024
#define MROWS   64                   // rows per CTA
#define NCTAS   (N_ROWS / MROWS)     // 512
#define NCHUNK  64                   // codes per chunk
#define NCHUNKS (KCODES / NCHUNK)    // 16
#define KD      256                  // emb storage: [hi 128 | lo 128]
#define NT      256                  // threads per CTA (8 warps)
#define ATS     132                  // A fragment-tile stride (128 + 4 pad)
#define BTS     66                   // B fragment-tile stride (64 + 2 pad)

__device__ float g_esq[KCODES];
__device__ __align__(16) float g_emb2[KCODES * KD];   // [k][hi d0..127 | lo d0..127]
__device__ float g_partials[NCTAS];
__device__ int   g_done;                              // zero-init; reset by last block

// smem float offsets
#define SF_A     0                    // 4 mtiles * 32 ks * 132 = 16896
#define SF_B0    16896                // 16896
#define SF_B1    33792                // 16896
#define SF_ESQ   50688                // 1024
#define SF_XSQ   51712                // 64
#define SF_CV    51776                // 512
#define SF_CK    52288                // 512
#define SF_CD    52800                // 512
#define SF_KW    53312                // 64
#define SF_LP    53376                // 64
#define SF_RED   53440                // 16
#define SF_TOTAL 53456                // floats -> 213824 bytes

__device__ __forceinline__ float tf32f(float f) {
    uint32_t r;
    asm("cvt.rna.tf32.f32 %0, %1;" : "=r"(r) : "f"(f));
    return __uint_as_float(r);
}

#define MMA_TF32(accp, av, b0, b1)                                             \
    asm volatile(                                                              \
        "mma.sync.aligned.m16n8k8.row.col.f32.tf32.tf32.f32 "                  \
        "{%0,%1,%2,%3}, {%4,%5,%6,%7}, {%8,%9}, {%0,%1,%2,%3};"                \
        : "+f"((accp)[0]), "+f"((accp)[1]), "+f"((accp)[2]), "+f"((accp)[3])   \
        : "r"(__float_as_uint((av).x)), "r"(__float_as_uint((av).y)),          \
          "r"(__float_as_uint((av).z)), "r"(__float_as_uint((av).w)),          \
          "r"(__float_as_uint(b0)), "r"(__float_as_uint(b1)))

// ---------------- prep: esq + tf32 split, warp-per-code ----------------
__global__ void prep_kernel(const float* __restrict__ emb) {
    int w = (blockIdx.x * blockDim.x + threadIdx.x) >> 5;   // code
    int lane = threadIdx.x & 31;
    if (w >= KCODES) return;
    float4 v = reinterpret_cast<const float4*>(emb + (size_t)w * DIM)[lane];
    float s = fmaf(v.x, v.x, fmaf(v.y, v.y, fmaf(v.z, v.z, v.w * v.w)));
#pragma unroll
    for (int o = 16; o; o >>= 1) s += __shfl_xor_sync(0xFFFFFFFFu, s, o);
    if (lane == 0) g_esq[w] = s;
    float hx = tf32f(v.x), hy = tf32f(v.y), hz = tf32f(v.z), hw = tf32f(v.w);
    float* dst = g_emb2 + (size_t)w * KD + 4 * lane;
    dst[0] = hx; dst[1] = hy; dst[2] = hz; dst[3] = hw;
    dst[128 + 0] = tf32f(v.x - hx); dst[128 + 1] = tf32f(v.y - hy);
    dst[128 + 2] = tf32f(v.z - hz); dst[128 + 3] = tf32f(v.w - hw);
}

// ---------------- main kernel ----------------
__device__ __forceinline__ void load_b(float* bs, int chunk, int tid) {
    const float4* e2 = reinterpret_cast<const float4*>(g_emb2);
#pragma unroll 4
    for (int i = 0; i < 16; i++) {
        int f = i * NT + tid;           // 0..4095 float4
        int c = f >> 6;                 // code 0..63
        int q = f & 63;
        float4 v = e2[(size_t)(chunk * NCHUNK + c) * (KD / 4) + q];
        int base = ((c >> 3) * 32 + (q >> 1)) * BTS + (c & 7) * 8 + (q & 1);
        bs[base + 0] = v.x;
        bs[base + 2] = v.y;
        bs[base + 4] = v.z;
        bs[base + 6] = v.w;
    }
}

__global__ __launch_bounds__(NT, 1)
void vq_mma_kernel(const float* __restrict__ x, const float* __restrict__ emb,
                   float* __restrict__ outQ, float* __restrict__ outLoss,
                   float* __restrict__ outIdx) {
    extern __shared__ float sm[];
    float* As    = sm + SF_A;
    float* esqs  = sm + SF_ESQ;
    float* xsqs  = sm + SF_XSQ;
    float* candV = sm + SF_CV;
    int*   candK = reinterpret_cast<int*>(sm + SF_CK);
    float* candD = sm + SF_CD;
    int*   kw    = reinterpret_cast<int*>(sm + SF_KW);
    float* lp    = sm + SF_LP;
    float* red   = sm + SF_RED;

    const int tid  = threadIdx.x;
    const int lane = tid & 31;
    const int warp = tid >> 5;
    const int wm = warp >> 1;                   // 0..3: m16-tile
    const int wn = warp & 1;                    // 0..1: n32-half
    const int gid = lane >> 2, tig = lane & 3;
    const int r0 = blockIdx.x * MROWS;

    for (int i = tid; i < KCODES; i += NT) esqs[i] = g_esq[i];

    // ---- A fill: fragment-major (layout identical to the R14 passing kernel)
    const float4* x4 = reinterpret_cast<const float4*>(x + (size_t)r0 * DIM);
#pragma unroll
    for (int i = 0; i < 8; i++) {
        int f = i * NT + tid;           // 0..2047 float4
        int r = f >> 5, c4 = f & 31;
        float4 v = x4[f];
        float hx = tf32f(v.x), hy = tf32f(v.y), hz = tf32f(v.z), hw = tf32f(v.w);
        int mtile = r >> 4, mr = r & 15;
        int g = mr & 7, slot = (mr >> 3) + 2 * (c4 & 1);
        int bh = (mtile * 32 + (c4 >> 1)) * ATS + g * 16 + slot;       // hi
        int bl = bh + 16 * ATS;                                        // lo
        As[bh + 0]  = hx; As[bh + 4]  = hy; As[bh + 8]  = hz; As[bh + 12] = hw;
        As[bl + 0]  = tf32f(v.x - hx); As[bl + 4]  = tf32f(v.y - hy);
        As[bl + 8]  = tf32f(v.z - hz); As[bl + 12] = tf32f(v.w - hw);
    }

    // ---- per-row |x|^2 (same formula/order as the R2 passing kernel)
    if (tid < MROWS) {
        const float4* xr = reinterpret_cast<const float4*>(x + (size_t)(r0 + tid) * DIM);
        float a0 = 0.f, a1 = 0.f, a2 = 0.f, a3 = 0.f;
#pragma unroll
        for (int i = 0; i < 32; i++) {
            float4 v = xr[i];
            a0 = fmaf(v.x, v.x, a0); a1 = fmaf(v.y, v.y, a1);
            a2 = fmaf(v.z, v.z, a2); a3 = fmaf(v.w, v.w, a3);
        }
        xsqs[tid] = (a0 + a1) + (a2 + a3);
    }

    load_b(sm + SF_B0, 0, tid);
    __syncthreads();

    // ---- A fragments -> registers, once (explicit: prevents ptxas spill chaos)
    // areg[ks]    = hi fragment for k-step ks
    // areg[16+ks] = lo fragment
    float4 areg[32];
#pragma unroll
    for (int g2 = 0; g2 < 2; g2++)
#pragma unroll
        for (int ks = 0; ks < 16; ks++)
            areg[g2 * 16 + ks] = *reinterpret_cast<const float4*>(
                &As[(wm * 32 + g2 * 16 + ks) * ATS + (gid * 4 + tig) * 4]);

    float xsl0 = xsqs[wm * 16 + gid];
    float xsl1 = xsqs[wm * 16 + gid + 8];

    float best[2] = {3.4e38f, 3.4e38f}, bdot[2] = {0.f, 0.f};
    int bk[2] = {0, 0};

#pragma unroll 1
    for (int ch = 0; ch < NCHUNKS; ch++) {
        if (ch + 1 < NCHUNKS) load_b(sm + ((ch + 1) & 1 ? SF_B1 : SF_B0), ch + 1, tid);

        const float* B = sm + ((ch & 1) ? SF_B1 : SF_B0);
        float acc[4][4];
#pragma unroll
        for (int nt = 0; nt < 4; nt++)
#pragma unroll
            for (int j = 0; j < 4; j++) acc[nt][j] = 0.f;

        // 3-group split-tf32 with B-hi reuse:
        //   per ks: bh loaded once, consumed by hi_a*bh AND lo_a*bh; then hi_a*bl.
#pragma unroll
        for (int ks = 0; ks < 16; ks++) {
            float2 bh[4];
#pragma unroll
            for (int nt = 0; nt < 4; nt++)
                bh[nt] = *reinterpret_cast<const float2*>(
                    &B[((wn * 4 + nt) * 32 + ks) * BTS + (gid * 4 + tig) * 2]);
            const float4 ah = areg[ks];
            const float4 al = areg[16 + ks];
#pragma unroll
            for (int nt = 0; nt < 4; nt++) MMA_TF32(acc[nt], ah, bh[nt].x, bh[nt].y);
#pragma unroll
            for (int nt = 0; nt < 4; nt++) MMA_TF32(acc[nt], al, bh[nt].x, bh[nt].y);
#pragma unroll
            for (int nt = 0; nt < 4; nt++) {
                float2 bl = *reinterpret_cast<const float2*>(
                    &B[((wn * 4 + nt) * 32 + 16 + ks) * BTS + (gid * 4 + tig) * 2]);
                MMA_TF32(acc[nt], ah, bl.x, bl.y);
            }
        }

        // fold into running argmin (ascending k per thread; strict < => first index)
#pragma unroll
        for (int nt = 0; nt < 4; nt++)
#pragma unroll
            for (int jj = 0; jj < 2; jj++) {
                int k = ch * NCHUNK + wn * 32 + nt * 8 + tig * 2 + jj;
                float e = esqs[k];
                float d0 = acc[nt][jj];            // row gid
                float d1 = acc[nt][2 + jj];        // row gid+8
                float v0 = (xsl0 - 2.0f * d0) + e;
                float v1 = (xsl1 - 2.0f * d1) + e;
                if (v0 < best[0]) { best[0] = v0; bk[0] = k; bdot[0] = d0; }
                if (v1 < best[1]) { best[1] = v1; bk[1] = k; bdot[1] = d1; }
            }
        __syncthreads();
    }

    // ---- cross-thread reduce: 8 candidate slots per row (wn x tig)
#pragma unroll
    for (int half = 0; half < 2; half++) {
        int rloc = wm * 16 + gid + half * 8;
        int slot = wn * 4 + tig;
        candV[rloc * 8 + slot] = best[half];
        candK[rloc * 8 + slot] = bk[half];
        candD[rloc * 8 + slot] = bdot[half];
    }
    __syncthreads();

    if (tid < MROWS) {
        float bv = candV[tid * 8];
        int   bkk = candK[tid * 8];
        float bd = candD[tid * 8];
#pragma unroll
        for (int s = 1; s < 8; s++) {
            float v = candV[tid * 8 + s];
            int   k2 = candK[tid * 8 + s];
            if (v < bv || (v == bv && k2 < bkk)) { bv = v; bkk = k2; bd = candD[tid * 8 + s]; }
        }
        kw[tid] = bkk;
        lp[tid] = fmaf(-2.0f, bd, xsqs[tid]) + esqs[bkk];
        if (outIdx != nullptr) outIdx[r0 + tid] = (float)bkk;
    }
    __syncthreads();

    // block partial
    if (tid == 0) {
        float s = 0.f;
        for (int r = 0; r < MROWS; r++) s += lp[r];
        g_partials[blockIdx.x] = s;
        __threadfence();
        int old = atomicAdd(&g_done, 1);
        red[8] = (old == NCTAS - 1) ? 1.0f : 0.0f;
    }

    // ---- quantized gather (emb L2-resident)
    const float4* e4 = reinterpret_cast<const float4*>(emb);
    float4* o4 = reinterpret_cast<float4*>(outQ) + (size_t)r0 * 32;
#pragma unroll 4
    for (int i = 0; i < 8; i++) {
        int f = i * NT + tid;
        int r = f >> 5, d4 = f & 31;
        o4[f] = e4[(size_t)kw[r] * 32 + d4];
    }

    // ---- last block finalizes the loss (deterministic fixed-order reduction)
    __syncthreads();
    if (red[8] != 0.0f) {
        __threadfence();
        float s = g_partials[tid] + g_partials[tid + NT];   // NCTAS = 2*NT
#pragma unroll
        for (int o = 16; o; o >>= 1) s += __shfl_xor_sync(0xFFFFFFFFu, s, o);
        if (lane == 0) red[warp] = s;
        __syncthreads();
        if (tid == 0) {
            float t = 0.f;
#pragma unroll
            for (int w2 = 0; w2 < 8; w2++) t += red[w2];
            float d = t / (float)((size_t)N_ROWS * DIM);
            if (outLoss != nullptr) outLoss[0] = d + 0.25f * d;
            g_done = 0;                                     // reset for next replay
        }
    }
}

extern "C" void kernel_launch(void* const* d_in, const int* in_sizes, int n_in,
                              void* d_out, int out_size) {
    const float* x   = (const float*)d_in[0];
    const float* emb = (const float*)d_in[1];
    if (n_in >= 2 && in_sizes[0] == KCODES * DIM && in_sizes[1] == N_ROWS * DIM) {
        const float* t = x; x = emb; emb = t;
    }

    float* out = (float*)d_out;
    float* outQ = out;
    float* outLoss = nullptr;
    float* outIdx = nullptr;
    if (out_size > N_ROWS * DIM) outLoss = out + (size_t)N_ROWS * DIM;
    if (out_size >= N_ROWS * DIM + 1 + N_ROWS) outIdx = out + (size_t)N_ROWS * DIM + 1;

    cudaFuncSetAttribute(vq_mma_kernel, cudaFuncAttributeMaxDynamicSharedMemorySize,
                         SF_TOTAL * (int)sizeof(float));

    prep_kernel<<<KCODES * 32 / NT, NT>>>(emb);
    vq_mma_kernel<<<NCTAS, NT, SF_TOTAL * sizeof(float)>>>(x, emb, outQ, outLoss, outIdx);
}